// round 6
// baseline (speedup 1.0000x reference)
#include <cuda_runtime.h>
#include <cuda_bf16.h>
#include <cstdint>
#include <math.h>

// ───────────────────────── problem constants ─────────────────────────
constexpr int Bsz = 4, S = 2048, E = 1024, D = 1024;

// ───────────────────────── device scratch (no allocs) ────────────────
__device__ __nv_bfloat16 g_xh[(size_t)Bsz * S * E];
__device__ __nv_bfloat16 g_xl[(size_t)Bsz * S * E];
__device__ __nv_bfloat16 g_Wh[(size_t)3 * E * D];   // [z][n][k] (transposed)
__device__ __nv_bfloat16 g_Wl[(size_t)3 * E * D];
__device__ __nv_bfloat16 g_qh[(size_t)Bsz * S * D];
__device__ __nv_bfloat16 g_ql[(size_t)Bsz * S * D];
__device__ __nv_bfloat16 g_kh[(size_t)Bsz * S * D];
__device__ __nv_bfloat16 g_kl[(size_t)Bsz * S * D];
__device__ __nv_bfloat16 g_vh[(size_t)Bsz * D * S]; // [b][d][s] (V transposed)
__device__ __nv_bfloat16 g_vl[(size_t)Bsz * D * S];
__device__ float         g_sc[(size_t)Bsz * S * S]; // masked scaled scores
__device__ __nv_bfloat16 g_ph[(size_t)Bsz * S * S]; // probs hi/lo
__device__ __nv_bfloat16 g_pl[(size_t)Bsz * S * S];

// ───────────────────────── tile config ───────────────────────────────
constexpr int BM = 128, BN = 128, BK = 32, NTH = 256, NSTAGE = 4;
constexpr int RS_B = 80;                         // smem row stride in bytes (32 bf16 + pad)
constexpr int PLANE_B = 128 * RS_B;              // 10240 B per operand plane
constexpr int STAGE_B = 4 * PLANE_B;             // Ah, Al, Bh, Bl
constexpr int SMEM_TOTAL = NSTAGE * STAGE_B;     // 163840 B

// ───────────────────────── PTX helpers ───────────────────────────────
__device__ __forceinline__ uint32_t s2u(const void* p) {
    uint32_t a;
    asm("{ .reg .u64 t; cvta.to.shared.u64 t, %1; cvt.u32.u64 %0, t; }" : "=r"(a) : "l"(p));
    return a;
}
__device__ __forceinline__ void cp_async16(uint32_t dst, const void* src) {
    asm volatile("cp.async.ca.shared.global [%0], [%1], 16;" :: "r"(dst), "l"(src) : "memory");
}
__device__ __forceinline__ void cp_commit() {
    asm volatile("cp.async.commit_group;" ::: "memory");
}
__device__ __forceinline__ void cp_wait2() {
    asm volatile("cp.async.wait_group 2;" ::: "memory");
}
__device__ __forceinline__ void ldmatrix4(uint32_t* r, uint32_t addr) {
    asm volatile("ldmatrix.sync.aligned.m8n8.x4.shared.b16 {%0,%1,%2,%3}, [%4];"
                 : "=r"(r[0]), "=r"(r[1]), "=r"(r[2]), "=r"(r[3]) : "r"(addr));
}
__device__ __forceinline__ void ldmatrix2(uint32_t* r, uint32_t addr) {
    asm volatile("ldmatrix.sync.aligned.m8n8.x2.shared.b16 {%0,%1}, [%2];"
                 : "=r"(r[0]), "=r"(r[1]) : "r"(addr));
}
__device__ __forceinline__ void mma16816(float* c, const uint32_t* a, const uint32_t* b) {
    asm volatile(
        "mma.sync.aligned.m16n8k16.row.col.f32.bf16.bf16.f32 "
        "{%0,%1,%2,%3}, {%4,%5,%6,%7}, {%8,%9}, {%0,%1,%2,%3};"
        : "+f"(c[0]), "+f"(c[1]), "+f"(c[2]), "+f"(c[3])
        : "r"(a[0]), "r"(a[1]), "r"(a[2]), "r"(a[3]), "r"(b[0]), "r"(b[1]));
}
__device__ __forceinline__ void split2(float v, __nv_bfloat16& h, __nv_bfloat16& l) {
    h = __float2bfloat16(v);
    l = __float2bfloat16(v - __bfloat162float(h));
}

// ───────────────────────── GEMM ──────────────────────────────────────
// C[m][n] = sum_k A[m][k] * B[n][k], bf16x3 split (AhBh + AhBl + AlBh).
// OP: 0=Q proj, 1=K proj, 2=V proj (transposed output), 3=scores, 4=PV
template <int OP>
__global__ __launch_bounds__(NTH, 1) void gemm_kernel(
    const float* __restrict__ bias,
    const int*   __restrict__ mask,
    float*       __restrict__ outF)
{
    extern __shared__ char smem[];
    const uint32_t sbase = s2u(smem);
    const int tid = threadIdx.x;
    const int wid = tid >> 5, lane = tid & 31;
    const size_t z = blockIdx.z;

    // operand binding
    const __nv_bfloat16 *Ah, *Al, *Bh, *Bl;
    int Kdim;
    if (OP == 0) { Ah = g_xh; Al = g_xl; Bh = g_Wh; Bl = g_Wl; Kdim = E; }
    else if (OP == 1) { Ah = g_xh; Al = g_xl; Bh = g_Wh + (size_t)E * D; Bl = g_Wl + (size_t)E * D; Kdim = E; }
    else if (OP == 2) { Ah = g_Wh + (size_t)2 * E * D; Al = g_Wl + (size_t)2 * E * D; Bh = g_xh; Bl = g_xl; Kdim = E; }
    else if (OP == 3) { Ah = g_qh + z * (size_t)S * D; Al = g_ql + z * (size_t)S * D;
                        Bh = g_kh + z * (size_t)S * D; Bl = g_kl + z * (size_t)S * D; Kdim = D; }
    else              { Ah = g_ph + z * (size_t)S * S; Al = g_pl + z * (size_t)S * S;
                        Bh = g_vh + z * (size_t)D * S; Bl = g_vl + z * (size_t)D * S; Kdim = S; }

    const int row0 = blockIdx.y * BM;
    const int col0 = blockIdx.x * BN;
    const int NC = Kdim / BK;

    auto load_stage = [&](int c, int st) {
        const int k0 = c * BK;
        const uint32_t stb = sbase + (uint32_t)st * STAGE_B;
#pragma unroll
        for (int j = 0; j < 8; j++) {
            const int pl = j >> 1;
            const int idx = ((j & 1) << 8) + tid;    // 0..511
            const int r = idx >> 2, u = idx & 3;
            const __nv_bfloat16* src;
            if (pl == 0)      src = Ah + (size_t)(row0 + r) * Kdim;
            else if (pl == 1) src = Al + (size_t)(row0 + r) * Kdim;
            else if (pl == 2) src = Bh + (size_t)(col0 + r) * Kdim;
            else              src = Bl + (size_t)(col0 + r) * Kdim;
            src += k0 + u * 8;
            cp_async16(stb + pl * PLANE_B + r * RS_B + u * 16, src);
        }
    };

    float acc[4][4][4];
#pragma unroll
    for (int i = 0; i < 4; i++)
#pragma unroll
        for (int j = 0; j < 4; j++)
#pragma unroll
            for (int t = 0; t < 4; t++) acc[i][j][t] = 0.0f;

    // prologue: NSTAGE-1 chunks in flight
#pragma unroll
    for (int s = 0; s < NSTAGE - 1; s++) { load_stage(s, s); cp_commit(); }

    const int wm = (wid & 1) * 64;    // warp m-offset (2 warps in m)
    const int wn = (wid >> 1) * 32;   // warp n-offset (4 warps in n)

    for (int c = 0; c < NC; c++) {
        cp_wait2();
        __syncthreads();

        const uint32_t stb = sbase + (uint32_t)(c % NSTAGE) * STAGE_B;
        const uint32_t sAh = stb, sAl = stb + PLANE_B;
        const uint32_t sBh = stb + 2 * PLANE_B, sBl = stb + 3 * PLANE_B;

#pragma unroll
        for (int ks = 0; ks < 2; ks++) {
            uint32_t ah[4][4], al[4][4], bh[4][2], bl[4][2];
            const int arow = wm + (lane & 15);
            const int akb = (ks * 16 + (lane >> 4) * 8) * 2;
#pragma unroll
            for (int i = 0; i < 4; i++) {
                ldmatrix4(ah[i], sAh + (arow + i * 16) * RS_B + akb);
                ldmatrix4(al[i], sAl + (arow + i * 16) * RS_B + akb);
            }
            const int brow = wn + (lane & 7);
            const int bkb = (ks * 16 + ((lane >> 3) & 1) * 8) * 2;
#pragma unroll
            for (int j = 0; j < 4; j++) {
                ldmatrix2(bh[j], sBh + (brow + j * 8) * RS_B + bkb);
                ldmatrix2(bl[j], sBl + (brow + j * 8) * RS_B + bkb);
            }
#pragma unroll
            for (int i = 0; i < 4; i++)
#pragma unroll
                for (int j = 0; j < 4; j++) {
                    mma16816(acc[i][j], ah[i], bh[j]);
                    mma16816(acc[i][j], ah[i], bl[j]);
                    mma16816(acc[i][j], al[i], bh[j]);
                }
        }

        if (c + NSTAGE - 1 < NC) load_stage(c + NSTAGE - 1, (c + NSTAGE - 1) % NSTAGE);
        cp_commit();
    }

    // ───────── epilogue ─────────
    __nv_bfloat16 *oH = nullptr, *oL = nullptr;
    if (OP == 0) { oH = g_qh; oL = g_ql; }
    else if (OP == 1) { oH = g_kh; oL = g_kl; }
    else if (OP == 2) { oH = g_vh; oL = g_vl; }

#pragma unroll
    for (int i = 0; i < 4; i++) {
        const int m = row0 + wm + i * 16 + (lane >> 2);
        float bm0 = 0.0f, bm1 = 0.0f;
        if (OP == 2) { bm0 = bias[m]; bm1 = bias[m + 8]; }
#pragma unroll
        for (int j = 0; j < 4; j++) {
            const int n = col0 + wn + j * 8 + 2 * (lane & 3);
            float v00 = acc[i][j][0], v01 = acc[i][j][1];   // row m,   cols n, n+1
            float v10 = acc[i][j][2], v11 = acc[i][j][3];   // row m+8, cols n, n+1

            if (OP == 0 || OP == 1) {
                float2 bb = *reinterpret_cast<const float2*>(bias + n);
                v00 += bb.x; v01 += bb.y; v10 += bb.x; v11 += bb.y;
                __nv_bfloat16 h0, l0, h1, l1;
                __nv_bfloat162 hv, lv;
                split2(v00, h0, l0); split2(v01, h1, l1);
                hv.x = h0; hv.y = h1; lv.x = l0; lv.y = l1;
                *reinterpret_cast<__nv_bfloat162*>(oH + (size_t)m * D + n) = hv;
                *reinterpret_cast<__nv_bfloat162*>(oL + (size_t)m * D + n) = lv;
                split2(v10, h0, l0); split2(v11, h1, l1);
                hv.x = h0; hv.y = h1; lv.x = l0; lv.y = l1;
                *reinterpret_cast<__nv_bfloat162*>(oH + (size_t)(m + 8) * D + n) = hv;
                *reinterpret_cast<__nv_bfloat162*>(oL + (size_t)(m + 8) * D + n) = lv;
            } else if (OP == 2) {
                // m = d index, n = global token: out[b][d][s]
                const int b = n >> 11, sI = n & 2047;
                const size_t base = (size_t)b * D * S + (size_t)m * S + sI;
                v00 += bm0; v01 += bm0; v10 += bm1; v11 += bm1;
                __nv_bfloat16 h0, l0, h1, l1;
                __nv_bfloat162 hv, lv;
                split2(v00, h0, l0); split2(v01, h1, l1);
                hv.x = h0; hv.y = h1; lv.x = l0; lv.y = l1;
                *reinterpret_cast<__nv_bfloat162*>(oH + base) = hv;
                *reinterpret_cast<__nv_bfloat162*>(oL + base) = lv;
                split2(v10, h0, l0); split2(v11, h1, l1);
                hv.x = h0; hv.y = h1; lv.x = l0; lv.y = l1;
                *reinterpret_cast<__nv_bfloat162*>(oH + base + 8 * S) = hv;
                *reinterpret_cast<__nv_bfloat162*>(oL + base + 8 * S) = lv;
            } else if (OP == 3) {
                const float sc = 1.0f / 1024.0f;
                const int* mrow = mask + z * (size_t)S * S;
                float* orow = g_sc + z * (size_t)S * S;
                int2 mk = *reinterpret_cast<const int2*>(mrow + (size_t)m * S + n);
                float2 o;
                o.x = (mk.x == 0) ? -INFINITY : v00 * sc;
                o.y = (mk.y == 0) ? -INFINITY : v01 * sc;
                *reinterpret_cast<float2*>(orow + (size_t)m * S + n) = o;
                mk = *reinterpret_cast<const int2*>(mrow + (size_t)(m + 8) * S + n);
                o.x = (mk.x == 0) ? -INFINITY : v10 * sc;
                o.y = (mk.y == 0) ? -INFINITY : v11 * sc;
                *reinterpret_cast<float2*>(orow + (size_t)(m + 8) * S + n) = o;
            } else {
                float* O = outF + z * (size_t)S * D;
                float2 o;
                o.x = v00; o.y = v01;
                *reinterpret_cast<float2*>(O + (size_t)m * D + n) = o;
                o.x = v10; o.y = v11;
                *reinterpret_cast<float2*>(O + (size_t)(m + 8) * D + n) = o;
            }
        }
    }
}

// ───────────────────────── conversion kernels ────────────────────────
__global__ __launch_bounds__(256) void convert_x_kernel(const float* __restrict__ x) {
    size_t i4 = (size_t)blockIdx.x * 256 + threadIdx.x;
    float4 v = reinterpret_cast<const float4*>(x)[i4];
    __nv_bfloat16 h0, l0, h1, l1, h2, l2, h3, l3;
    split2(v.x, h0, l0); split2(v.y, h1, l1);
    split2(v.z, h2, l2); split2(v.w, h3, l3);
    __nv_bfloat162* oh = reinterpret_cast<__nv_bfloat162*>(g_xh) + i4 * 2;
    __nv_bfloat162* ol = reinterpret_cast<__nv_bfloat162*>(g_xl) + i4 * 2;
    __nv_bfloat162 a, b;
    a.x = h0; a.y = h1; b.x = h2; b.y = h3;
    oh[0] = a; oh[1] = b;
    a.x = l0; a.y = l1; b.x = l2; b.y = l3;
    ol[0] = a; ol[1] = b;
}

// W [E][D] row-major -> planes [z][n][k] (transposed)
__global__ __launch_bounds__(256) void convert_w_kernel(
    const float* __restrict__ Wq, const float* __restrict__ Wk, const float* __restrict__ Wv)
{
    const float* W = (blockIdx.z == 0) ? Wq : (blockIdx.z == 1) ? Wk : Wv;
    __nv_bfloat16* oh = g_Wh + (size_t)blockIdx.z * E * D;
    __nv_bfloat16* ol = g_Wl + (size_t)blockIdx.z * E * D;

    __shared__ float t[32][33];
    const int tx = threadIdx.x & 31, ty = threadIdx.x >> 5;   // 32 x 8
#pragma unroll
    for (int i = 0; i < 4; i++) {
        int kk = blockIdx.y * 32 + ty + i * 8;
        t[ty + i * 8][tx] = W[(size_t)kk * D + blockIdx.x * 32 + tx];
    }
    __syncthreads();
#pragma unroll
    for (int i = 0; i < 4; i++) {
        int n  = blockIdx.x * 32 + ty + i * 8;
        int kk = blockIdx.y * 32 + tx;
        float v = t[tx][ty + i * 8];
        __nv_bfloat16 h, l;
        split2(v, h, l);
        oh[(size_t)n * E + kk] = h;
        ol[(size_t)n * E + kk] = l;
    }
}

// ───────────────────────── softmax ───────────────────────────────────
__global__ __launch_bounds__(256) void softmax_kernel() {
    const int b = blockIdx.y, q = blockIdx.x;
    const float* row = g_sc + ((size_t)b * S + q) * S;
    __nv_bfloat16* oh = g_ph + ((size_t)b * S + q) * S;
    __nv_bfloat16* ol = g_pl + ((size_t)b * S + q) * S;
    const int tid = threadIdx.x;

    __shared__ float red[256];

    float vals[8];
#pragma unroll
    for (int i = 0; i < 8; i++) vals[i] = row[tid + i * 256];

    float lmax = -INFINITY;
#pragma unroll
    for (int i = 0; i < 8; i++) lmax = fmaxf(lmax, vals[i]);
    red[tid] = lmax;
    __syncthreads();
    for (int st = 128; st > 0; st >>= 1) {
        if (tid < st) red[tid] = fmaxf(red[tid], red[tid + st]);
        __syncthreads();
    }
    const float mx = red[0];
    __syncthreads();

    float lsum = 0.0f;
#pragma unroll
    for (int i = 0; i < 8; i++) { vals[i] = expf(vals[i] - mx); lsum += vals[i]; }
    red[tid] = lsum;
    __syncthreads();
    for (int st = 128; st > 0; st >>= 1) {
        if (tid < st) red[tid] += red[tid + st];
        __syncthreads();
    }
    const float inv = 1.0f / red[0];

#pragma unroll
    for (int i = 0; i < 8; i++) {
        float p = vals[i] * inv;
        __nv_bfloat16 h, l;
        split2(p, h, l);
        oh[tid + i * 256] = h;
        ol[tid + i * 256] = l;
    }
}

// ───────────────────────── host launch ───────────────────────────────
extern "C" void kernel_launch(void* const* d_in, const int* in_sizes, int n_in,
                              void* d_out, int out_size)
{
    const float* x    = (const float*)d_in[0];
    const int*   mask = (const int*)  d_in[1];
    const float* Wq   = (const float*)d_in[2];
    const float* bq   = (const float*)d_in[3];
    const float* Wk   = (const float*)d_in[4];
    const float* bk   = (const float*)d_in[5];
    const float* Wv   = (const float*)d_in[6];
    const float* bv   = (const float*)d_in[7];
    float* out = (float*)d_out;

    cudaFuncSetAttribute(gemm_kernel<0>, cudaFuncAttributeMaxDynamicSharedMemorySize, SMEM_TOTAL);
    cudaFuncSetAttribute(gemm_kernel<1>, cudaFuncAttributeMaxDynamicSharedMemorySize, SMEM_TOTAL);
    cudaFuncSetAttribute(gemm_kernel<2>, cudaFuncAttributeMaxDynamicSharedMemorySize, SMEM_TOTAL);
    cudaFuncSetAttribute(gemm_kernel<3>, cudaFuncAttributeMaxDynamicSharedMemorySize, SMEM_TOTAL);
    cudaFuncSetAttribute(gemm_kernel<4>, cudaFuncAttributeMaxDynamicSharedMemorySize, SMEM_TOTAL);

    // 1) fp32 -> hi/lo bf16 planes
    convert_x_kernel<<<(unsigned)((size_t)Bsz * S * E / 4 / 256), 256>>>(x);
    convert_w_kernel<<<dim3(D / 32, E / 32, 3), 256>>>(Wq, Wk, Wv);

    // 2) projections: Q, K ([token][d]), V (transposed, [b][d][s])
    gemm_kernel<0><<<dim3(D / BN, (Bsz * S) / BM, 1), NTH, SMEM_TOTAL>>>(bq, nullptr, nullptr);
    gemm_kernel<1><<<dim3(D / BN, (Bsz * S) / BM, 1), NTH, SMEM_TOTAL>>>(bk, nullptr, nullptr);
    gemm_kernel<2><<<dim3((Bsz * S) / BN, D / BM, 1), NTH, SMEM_TOTAL>>>(bv, nullptr, nullptr);

    // 3) scores = QK^T / 1024, masked
    gemm_kernel<3><<<dim3(S / BN, S / BM, Bsz), NTH, SMEM_TOTAL>>>(nullptr, mask, nullptr);

    // 4) softmax -> prob planes
    softmax_kernel<<<dim3(S, Bsz), 256>>>();

    // 5) out = P @ V
    gemm_kernel<4><<<dim3(D / BN, S / BM, Bsz), NTH, SMEM_TOTAL>>>(nullptr, nullptr, out);
}

// round 7
// speedup vs baseline: 2.2767x; 2.2767x over previous
#include <cuda_runtime.h>
#include <cuda_fp16.h>
#include <cstdint>
#include <math.h>

// ───────────────────────── problem constants ─────────────────────────
constexpr int Bsz = 4, S = 2048, E = 1024, D = 1024;

// ───────────────────────── device scratch (no allocs) ────────────────
__device__ __half g_x[(size_t)Bsz * S * E];
__device__ __half g_W[(size_t)3 * E * D];        // [z][n][k] (transposed)
__device__ __half g_q[(size_t)Bsz * S * D];
__device__ __half g_k[(size_t)Bsz * S * D];
__device__ __half g_v[(size_t)Bsz * D * S];      // [b][d][s] (V transposed)
__device__ float  g_sc[(size_t)Bsz * S * S];     // masked scaled scores
__device__ __half g_p[(size_t)Bsz * S * S];      // probs

// ───────────────────────── tile config ───────────────────────────────
constexpr int BM = 128, BN = 128, BK = 32, NTH = 256, NSTAGE = 4;
constexpr int RS_B = 80;                         // smem row stride bytes (64 + 16 pad)
constexpr int PLANE_B = 128 * RS_B;              // 10240 B per operand plane
constexpr int STAGE_B = 2 * PLANE_B;             // A, B
constexpr int SMEM_TOTAL = NSTAGE * STAGE_B;     // 81920 B

// ───────────────────────── PTX helpers ───────────────────────────────
__device__ __forceinline__ uint32_t s2u(const void* p) {
    uint32_t a;
    asm("{ .reg .u64 t; cvta.to.shared.u64 t, %1; cvt.u32.u64 %0, t; }" : "=r"(a) : "l"(p));
    return a;
}
__device__ __forceinline__ void cp_async16(uint32_t dst, const void* src) {
    asm volatile("cp.async.ca.shared.global [%0], [%1], 16;" :: "r"(dst), "l"(src) : "memory");
}
__device__ __forceinline__ void cp_commit() {
    asm volatile("cp.async.commit_group;" ::: "memory");
}
__device__ __forceinline__ void cp_wait2() {
    asm volatile("cp.async.wait_group 2;" ::: "memory");
}
__device__ __forceinline__ void ldmatrix4(uint32_t* r, uint32_t addr) {
    asm volatile("ldmatrix.sync.aligned.m8n8.x4.shared.b16 {%0,%1,%2,%3}, [%4];"
                 : "=r"(r[0]), "=r"(r[1]), "=r"(r[2]), "=r"(r[3]) : "r"(addr));
}
__device__ __forceinline__ void ldmatrix2(uint32_t* r, uint32_t addr) {
    asm volatile("ldmatrix.sync.aligned.m8n8.x2.shared.b16 {%0,%1}, [%2];"
                 : "=r"(r[0]), "=r"(r[1]) : "r"(addr));
}
__device__ __forceinline__ void mma16816(float* c, const uint32_t* a, const uint32_t* b) {
    asm volatile(
        "mma.sync.aligned.m16n8k16.row.col.f32.f16.f16.f32 "
        "{%0,%1,%2,%3}, {%4,%5,%6,%7}, {%8,%9}, {%0,%1,%2,%3};"
        : "+f"(c[0]), "+f"(c[1]), "+f"(c[2]), "+f"(c[3])
        : "r"(a[0]), "r"(a[1]), "r"(a[2]), "r"(a[3]), "r"(b[0]), "r"(b[1]));
}

// ───────────────────────── GEMM ──────────────────────────────────────
// C[m][n] = sum_k A[m][k] * B[n][k], fp16 operands, fp32 accumulate.
// OP: 0=Q proj, 1=K proj, 2=V proj (transposed out), 3=scores, 4=PV
template <int OP>
__global__ __launch_bounds__(NTH, 2) void gemm_kernel(
    const float* __restrict__ bias,
    const int*   __restrict__ mask,
    float*       __restrict__ outF)
{
    extern __shared__ char smem[];
    const uint32_t sbase = s2u(smem);
    const int tid = threadIdx.x;
    const int wid = tid >> 5, lane = tid & 31;
    const size_t z = blockIdx.z;

    const __half *A, *B;
    int Kdim;
    if (OP == 0)      { A = g_x; B = g_W;                    Kdim = E; }
    else if (OP == 1) { A = g_x; B = g_W + (size_t)E * D;    Kdim = E; }
    else if (OP == 2) { A = g_W + (size_t)2 * E * D; B = g_x; Kdim = E; }
    else if (OP == 3) { A = g_q + z * (size_t)S * D; B = g_k + z * (size_t)S * D; Kdim = D; }
    else              { A = g_p + z * (size_t)S * S; B = g_v + z * (size_t)D * S; Kdim = S; }

    const int row0 = blockIdx.y * BM;
    const int col0 = blockIdx.x * BN;
    const int NC = Kdim / BK;

    auto load_stage = [&](int c, int st) {
        const int k0 = c * BK;
        const uint32_t stb = sbase + (uint32_t)st * STAGE_B;
#pragma unroll
        for (int j = 0; j < 4; j++) {
            const int pl = j >> 1;                   // 0 = A, 1 = B
            const int idx = ((j & 1) << 8) + tid;    // 0..511
            const int r = idx >> 2, u = idx & 3;
            const __half* src = (pl == 0)
                ? A + (size_t)(row0 + r) * Kdim
                : B + (size_t)(col0 + r) * Kdim;
            src += k0 + u * 8;
            cp_async16(stb + pl * PLANE_B + r * RS_B + u * 16, src);
        }
    };

    float acc[4][4][4];
#pragma unroll
    for (int i = 0; i < 4; i++)
#pragma unroll
        for (int j = 0; j < 4; j++)
#pragma unroll
            for (int t = 0; t < 4; t++) acc[i][j][t] = 0.0f;

#pragma unroll
    for (int s = 0; s < NSTAGE - 1; s++) { load_stage(s, s); cp_commit(); }

    const int wm = (wid & 1) * 64;    // 2 warps in m
    const int wn = (wid >> 1) * 32;   // 4 warps in n

    for (int c = 0; c < NC; c++) {
        cp_wait2();
        __syncthreads();

        const uint32_t stb = sbase + (uint32_t)(c % NSTAGE) * STAGE_B;
        const uint32_t sA = stb, sB = stb + PLANE_B;

#pragma unroll
        for (int ks = 0; ks < 2; ks++) {
            uint32_t a[4][4], b[4][2];
            const int arow = wm + (lane & 15);
            const int akb = (ks * 16 + (lane >> 4) * 8) * 2;
#pragma unroll
            for (int i = 0; i < 4; i++)
                ldmatrix4(a[i], sA + (arow + i * 16) * RS_B + akb);
            const int brow = wn + (lane & 7);
            const int bkb = (ks * 16 + ((lane >> 3) & 1) * 8) * 2;
#pragma unroll
            for (int j = 0; j < 4; j++)
                ldmatrix2(b[j], sB + (brow + j * 8) * RS_B + bkb);
#pragma unroll
            for (int i = 0; i < 4; i++)
#pragma unroll
                for (int j = 0; j < 4; j++)
                    mma16816(acc[i][j], a[i], b[j]);
        }

        if (c + NSTAGE - 1 < NC) load_stage(c + NSTAGE - 1, (c + NSTAGE - 1) % NSTAGE);
        cp_commit();
        __syncthreads();
    }

    // ───────── epilogue ─────────
    __half* oH = nullptr;
    if (OP == 0) oH = g_q;
    else if (OP == 1) oH = g_k;
    else if (OP == 2) oH = g_v;

#pragma unroll
    for (int i = 0; i < 4; i++) {
        const int m = row0 + wm + i * 16 + (lane >> 2);
        float bm0 = 0.0f, bm1 = 0.0f;
        if (OP == 2) { bm0 = bias[m]; bm1 = bias[m + 8]; }
#pragma unroll
        for (int j = 0; j < 4; j++) {
            const int n = col0 + wn + j * 8 + 2 * (lane & 3);
            float v00 = acc[i][j][0], v01 = acc[i][j][1];   // row m
            float v10 = acc[i][j][2], v11 = acc[i][j][3];   // row m+8

            if (OP == 0 || OP == 1) {
                float2 bb = *reinterpret_cast<const float2*>(bias + n);
                *reinterpret_cast<__half2*>(oH + (size_t)m * D + n) =
                    __floats2half2_rn(v00 + bb.x, v01 + bb.y);
                *reinterpret_cast<__half2*>(oH + (size_t)(m + 8) * D + n) =
                    __floats2half2_rn(v10 + bb.x, v11 + bb.y);
            } else if (OP == 2) {
                // m = d index, n = global token: out[b][d][s]
                const int b = n >> 11, sI = n & 2047;
                const size_t base = (size_t)b * D * S + (size_t)m * S + sI;
                *reinterpret_cast<__half2*>(oH + base) =
                    __floats2half2_rn(v00 + bm0, v01 + bm0);
                *reinterpret_cast<__half2*>(oH + base + 8 * S) =
                    __floats2half2_rn(v10 + bm1, v11 + bm1);
            } else if (OP == 3) {
                const float sc = 1.0f / 1024.0f;
                const int* mrow = mask + z * (size_t)S * S;
                float* orow = g_sc + z * (size_t)S * S;
                int2 mk = *reinterpret_cast<const int2*>(mrow + (size_t)m * S + n);
                float2 o;
                o.x = (mk.x == 0) ? -INFINITY : v00 * sc;
                o.y = (mk.y == 0) ? -INFINITY : v01 * sc;
                *reinterpret_cast<float2*>(orow + (size_t)m * S + n) = o;
                mk = *reinterpret_cast<const int2*>(mrow + (size_t)(m + 8) * S + n);
                o.x = (mk.x == 0) ? -INFINITY : v10 * sc;
                o.y = (mk.y == 0) ? -INFINITY : v11 * sc;
                *reinterpret_cast<float2*>(orow + (size_t)(m + 8) * S + n) = o;
            } else {
                float* O = outF + z * (size_t)S * D;
                float2 o;
                o.x = v00; o.y = v01;
                *reinterpret_cast<float2*>(O + (size_t)m * D + n) = o;
                o.x = v10; o.y = v11;
                *reinterpret_cast<float2*>(O + (size_t)(m + 8) * D + n) = o;
            }
        }
    }
}

// ───────────────────────── conversion kernels ────────────────────────
__global__ __launch_bounds__(256) void convert_x_kernel(const float* __restrict__ x) {
    size_t i4 = (size_t)blockIdx.x * 256 + threadIdx.x;
    float4 v = reinterpret_cast<const float4*>(x)[i4];
    __half2* o = reinterpret_cast<__half2*>(g_x) + i4 * 2;
    o[0] = __floats2half2_rn(v.x, v.y);
    o[1] = __floats2half2_rn(v.z, v.w);
}

// W [E][D] row-major -> [z][n][k] transposed fp16
__global__ __launch_bounds__(256) void convert_w_kernel(
    const float* __restrict__ Wq, const float* __restrict__ Wk, const float* __restrict__ Wv)
{
    const float* W = (blockIdx.z == 0) ? Wq : (blockIdx.z == 1) ? Wk : Wv;
    __half* o = g_W + (size_t)blockIdx.z * E * D;

    __shared__ float t[32][33];
    const int tx = threadIdx.x & 31, ty = threadIdx.x >> 5;   // 32 x 8
#pragma unroll
    for (int i = 0; i < 4; i++) {
        int kk = blockIdx.y * 32 + ty + i * 8;
        t[ty + i * 8][tx] = W[(size_t)kk * D + blockIdx.x * 32 + tx];
    }
    __syncthreads();
#pragma unroll
    for (int i = 0; i < 4; i++) {
        int n  = blockIdx.x * 32 + ty + i * 8;
        int kk = blockIdx.y * 32 + tx;
        o[(size_t)n * E + kk] = __float2half_rn(t[tx][ty + i * 8]);
    }
}

// ───────────────────────── softmax ───────────────────────────────────
__global__ __launch_bounds__(256) void softmax_kernel() {
    const int b = blockIdx.y, q = blockIdx.x;
    const float* row = g_sc + ((size_t)b * S + q) * S;
    __half* op = g_p + ((size_t)b * S + q) * S;
    const int tid = threadIdx.x;

    __shared__ float red[256];

    float vals[8];
#pragma unroll
    for (int i = 0; i < 8; i++) vals[i] = row[tid + i * 256];

    float lmax = -INFINITY;
#pragma unroll
    for (int i = 0; i < 8; i++) lmax = fmaxf(lmax, vals[i]);
    red[tid] = lmax;
    __syncthreads();
    for (int st = 128; st > 0; st >>= 1) {
        if (tid < st) red[tid] = fmaxf(red[tid], red[tid + st]);
        __syncthreads();
    }
    const float mx = red[0];
    __syncthreads();

    float lsum = 0.0f;
#pragma unroll
    for (int i = 0; i < 8; i++) { vals[i] = expf(vals[i] - mx); lsum += vals[i]; }
    red[tid] = lsum;
    __syncthreads();
    for (int st = 128; st > 0; st >>= 1) {
        if (tid < st) red[tid] += red[tid + st];
        __syncthreads();
    }
    const float inv = 1.0f / red[0];

#pragma unroll
    for (int i = 0; i < 8; i++)
        op[tid + i * 256] = __float2half_rn(vals[i] * inv);
}

// ───────────────────────── host launch ───────────────────────────────
extern "C" void kernel_launch(void* const* d_in, const int* in_sizes, int n_in,
                              void* d_out, int out_size)
{
    const float* x    = (const float*)d_in[0];
    const int*   mask = (const int*)  d_in[1];
    const float* Wq   = (const float*)d_in[2];
    const float* bq   = (const float*)d_in[3];
    const float* Wk   = (const float*)d_in[4];
    const float* bk   = (const float*)d_in[5];
    const float* Wv   = (const float*)d_in[6];
    const float* bv   = (const float*)d_in[7];
    float* out = (float*)d_out;

    cudaFuncSetAttribute(gemm_kernel<0>, cudaFuncAttributeMaxDynamicSharedMemorySize, SMEM_TOTAL);
    cudaFuncSetAttribute(gemm_kernel<1>, cudaFuncAttributeMaxDynamicSharedMemorySize, SMEM_TOTAL);
    cudaFuncSetAttribute(gemm_kernel<2>, cudaFuncAttributeMaxDynamicSharedMemorySize, SMEM_TOTAL);
    cudaFuncSetAttribute(gemm_kernel<3>, cudaFuncAttributeMaxDynamicSharedMemorySize, SMEM_TOTAL);
    cudaFuncSetAttribute(gemm_kernel<4>, cudaFuncAttributeMaxDynamicSharedMemorySize, SMEM_TOTAL);

    // 1) fp32 -> fp16
    convert_x_kernel<<<(unsigned)((size_t)Bsz * S * E / 4 / 256), 256>>>(x);
    convert_w_kernel<<<dim3(D / 32, E / 32, 3), 256>>>(Wq, Wk, Wv);

    // 2) projections: Q, K ([token][d]), V (transposed, [b][d][s])
    gemm_kernel<0><<<dim3(D / BN, (Bsz * S) / BM, 1), NTH, SMEM_TOTAL>>>(bq, nullptr, nullptr);
    gemm_kernel<1><<<dim3(D / BN, (Bsz * S) / BM, 1), NTH, SMEM_TOTAL>>>(bk, nullptr, nullptr);
    gemm_kernel<2><<<dim3((Bsz * S) / BN, D / BM, 1), NTH, SMEM_TOTAL>>>(bv, nullptr, nullptr);

    // 3) scores = QK^T / 1024, masked
    gemm_kernel<3><<<dim3(S / BN, S / BM, Bsz), NTH, SMEM_TOTAL>>>(nullptr, mask, nullptr);

    // 4) softmax -> fp16 probs
    softmax_kernel<<<dim3(S, Bsz), 256>>>();

    // 5) out = P @ V
    gemm_kernel<4><<<dim3(D / BN, S / BM, Bsz), NTH, SMEM_TOTAL>>>(nullptr, nullptr, out);
}

// round 8
// speedup vs baseline: 2.5804x; 1.1334x over previous
#include <cuda_runtime.h>
#include <cuda_fp16.h>
#include <cstdint>
#include <math.h>

// ───────────────────────── problem constants ─────────────────────────
constexpr int Bsz = 4, S = 2048, E = 1024, D = 1024;

// ───────────────────────── device scratch (no allocs) ────────────────
__device__ __half g_x[(size_t)Bsz * S * E];
__device__ __half g_W[(size_t)3 * E * D];        // [z][n][k] (transposed)
__device__ __half g_q[(size_t)Bsz * S * D];
__device__ __half g_k[(size_t)Bsz * S * D];
__device__ __half g_v[(size_t)Bsz * D * S];      // [b][d][s] (V transposed)
__device__ __half g_sc[(size_t)Bsz * S * S];     // masked scaled scores (fp16)
__device__ __half g_p[(size_t)Bsz * S * S];      // probs

// ───────────────────────── tile config ───────────────────────────────
constexpr int BM = 128, BN = 128, BK = 64, NTH = 256, NSTAGE = 3;
constexpr int RS_B = 144;                        // smem row stride bytes (128 + 16 pad)
constexpr int PLANE_B = 128 * RS_B;              // 18432 B per operand plane
constexpr int STAGE_B = 2 * PLANE_B;             // A, B
constexpr int SMEM_TOTAL = NSTAGE * STAGE_B;     // 110592 B

// ───────────────────────── PTX helpers ───────────────────────────────
__device__ __forceinline__ uint32_t s2u(const void* p) {
    uint32_t a;
    asm("{ .reg .u64 t; cvta.to.shared.u64 t, %1; cvt.u32.u64 %0, t; }" : "=r"(a) : "l"(p));
    return a;
}
__device__ __forceinline__ void cp_async16(uint32_t dst, const void* src) {
    asm volatile("cp.async.ca.shared.global [%0], [%1], 16;" :: "r"(dst), "l"(src) : "memory");
}
__device__ __forceinline__ void cp_commit() {
    asm volatile("cp.async.commit_group;" ::: "memory");
}
__device__ __forceinline__ void cp_wait1() {
    asm volatile("cp.async.wait_group 1;" ::: "memory");
}
__device__ __forceinline__ void ldmatrix4(uint32_t* r, uint32_t addr) {
    asm volatile("ldmatrix.sync.aligned.m8n8.x4.shared.b16 {%0,%1,%2,%3}, [%4];"
                 : "=r"(r[0]), "=r"(r[1]), "=r"(r[2]), "=r"(r[3]) : "r"(addr));
}
__device__ __forceinline__ void mma16816(float* c, const uint32_t* a, const uint32_t* b) {
    asm volatile(
        "mma.sync.aligned.m16n8k16.row.col.f32.f16.f16.f32 "
        "{%0,%1,%2,%3}, {%4,%5,%6,%7}, {%8,%9}, {%0,%1,%2,%3};"
        : "+f"(c[0]), "+f"(c[1]), "+f"(c[2]), "+f"(c[3])
        : "r"(a[0]), "r"(a[1]), "r"(a[2]), "r"(a[3]), "r"(b[0]), "r"(b[1]));
}

// ───────────────────────── GEMM ──────────────────────────────────────
// C[m][n] = sum_k A[m][k] * B[n][k], fp16 operands, fp32 accumulate.
// Warp tile 32x64: 4 warps in m, 2 in n.
// OP: 0=Q proj, 1=K proj, 2=V proj (transposed out), 3=scores, 4=PV
template <int OP>
__global__ __launch_bounds__(NTH, 2) void gemm_kernel(
    const float* __restrict__ bias,
    const int*   __restrict__ mask,
    float*       __restrict__ outF)
{
    extern __shared__ char smem[];
    const uint32_t sbase = s2u(smem);
    const int tid = threadIdx.x;
    const int wid = tid >> 5, lane = tid & 31;
    const size_t z = blockIdx.z;

    const __half *A, *B;
    int Kdim;
    if (OP == 0)      { A = g_x; B = g_W;                     Kdim = E; }
    else if (OP == 1) { A = g_x; B = g_W + (size_t)E * D;     Kdim = E; }
    else if (OP == 2) { A = g_W + (size_t)2 * E * D; B = g_x; Kdim = E; }
    else if (OP == 3) { A = g_q + z * (size_t)S * D; B = g_k + z * (size_t)S * D; Kdim = D; }
    else              { A = g_p + z * (size_t)S * S; B = g_v + z * (size_t)D * S; Kdim = S; }

    const int row0 = blockIdx.y * BM;
    const int col0 = blockIdx.x * BN;
    const int NC = Kdim / BK;

    auto load_stage = [&](int c, int st) {
        const int k0 = c * BK;
        const uint32_t stb = sbase + (uint32_t)st * STAGE_B;
#pragma unroll
        for (int p = 0; p < 2; p++) {
            const __half* base = (p == 0) ? A : B;
            const int r0g = (p == 0) ? row0 : col0;
#pragma unroll
            for (int t = 0; t < 4; t++) {
                const int idx = t * 256 + tid;       // 0..1023
                const int r = idx >> 3, u = idx & 7; // row, 16B-unit
                cp_async16(stb + p * PLANE_B + r * RS_B + u * 16,
                           base + (size_t)(r0g + r) * Kdim + k0 + u * 8);
            }
        }
    };

    float acc[2][8][4];
#pragma unroll
    for (int i = 0; i < 2; i++)
#pragma unroll
        for (int j = 0; j < 8; j++)
#pragma unroll
            for (int t = 0; t < 4; t++) acc[i][j][t] = 0.0f;

#pragma unroll
    for (int s = 0; s < NSTAGE - 1; s++) { load_stage(s, s); cp_commit(); }

    const int wm = (wid & 3) * 32;    // 4 warps in m
    const int wn = (wid >> 2) * 64;   // 2 warps in n

    // ldmatrix lane address components (constant across chunks)
    const int aRow = wm + (lane & 15);
    const int aK   = (lane >> 4) * 16;               // bytes
    const int bRow = wn + (lane & 7) + ((lane >> 4) << 3);
    const int bK   = ((lane >> 3) & 1) * 16;         // bytes

    for (int c = 0; c < NC; c++) {
        cp_wait1();
        __syncthreads();

        const uint32_t stb = sbase + (uint32_t)(c % NSTAGE) * STAGE_B;
        const uint32_t sA = stb, sB = stb + PLANE_B;

#pragma unroll
        for (int ks = 0; ks < 4; ks++) {
            uint32_t a[2][4], b[4][4];
#pragma unroll
            for (int i = 0; i < 2; i++)
                ldmatrix4(a[i], sA + (aRow + i * 16) * RS_B + ks * 32 + aK);
#pragma unroll
            for (int j = 0; j < 4; j++)
                ldmatrix4(b[j], sB + (bRow + j * 16) * RS_B + ks * 32 + bK);
#pragma unroll
            for (int i = 0; i < 2; i++)
#pragma unroll
                for (int j = 0; j < 4; j++) {
                    mma16816(acc[i][2 * j],     a[i], &b[j][0]);
                    mma16816(acc[i][2 * j + 1], a[i], &b[j][2]);
                }
        }

        if (c + NSTAGE - 1 < NC) load_stage(c + NSTAGE - 1, (c + NSTAGE - 1) % NSTAGE);
        cp_commit();
    }

    // ───────── epilogue ─────────
    __half* oH = nullptr;
    if (OP == 0) oH = g_q;
    else if (OP == 1) oH = g_k;
    else if (OP == 2) oH = g_v;

#pragma unroll
    for (int i = 0; i < 2; i++) {
        const int m = row0 + wm + i * 16 + (lane >> 2);
        float bm0 = 0.0f, bm1 = 0.0f;
        if (OP == 2) { bm0 = bias[m]; bm1 = bias[m + 8]; }
#pragma unroll
        for (int j = 0; j < 8; j++) {
            const int n = col0 + wn + j * 8 + 2 * (lane & 3);
            float v00 = acc[i][j][0], v01 = acc[i][j][1];   // row m
            float v10 = acc[i][j][2], v11 = acc[i][j][3];   // row m+8

            if (OP == 0 || OP == 1) {
                float2 bb = *reinterpret_cast<const float2*>(bias + n);
                *reinterpret_cast<__half2*>(oH + (size_t)m * D + n) =
                    __floats2half2_rn(v00 + bb.x, v01 + bb.y);
                *reinterpret_cast<__half2*>(oH + (size_t)(m + 8) * D + n) =
                    __floats2half2_rn(v10 + bb.x, v11 + bb.y);
            } else if (OP == 2) {
                // m = d index, n = global token: out[b][d][s]
                const int b = n >> 11, sI = n & 2047;
                const size_t base = (size_t)b * D * S + (size_t)m * S + sI;
                *reinterpret_cast<__half2*>(oH + base) =
                    __floats2half2_rn(v00 + bm0, v01 + bm0);
                *reinterpret_cast<__half2*>(oH + base + 8 * S) =
                    __floats2half2_rn(v10 + bm1, v11 + bm1);
            } else if (OP == 3) {
                const float sc = 1.0f / 1024.0f;
                const int* mrow = mask + z * (size_t)S * S;
                __half* orow = g_sc + z * (size_t)S * S;
                int2 mk = *reinterpret_cast<const int2*>(mrow + (size_t)m * S + n);
                *reinterpret_cast<__half2*>(orow + (size_t)m * S + n) =
                    __floats2half2_rn(mk.x == 0 ? -INFINITY : v00 * sc,
                                      mk.y == 0 ? -INFINITY : v01 * sc);
                mk = *reinterpret_cast<const int2*>(mrow + (size_t)(m + 8) * S + n);
                *reinterpret_cast<__half2*>(orow + (size_t)(m + 8) * S + n) =
                    __floats2half2_rn(mk.x == 0 ? -INFINITY : v10 * sc,
                                      mk.y == 0 ? -INFINITY : v11 * sc);
            } else {
                float* O = outF + z * (size_t)S * D;
                float2 o;
                o.x = v00; o.y = v01;
                *reinterpret_cast<float2*>(O + (size_t)m * D + n) = o;
                o.x = v10; o.y = v11;
                *reinterpret_cast<float2*>(O + (size_t)(m + 8) * D + n) = o;
            }
        }
    }
}

// ───────────────────────── conversion kernels ────────────────────────
__global__ __launch_bounds__(256) void convert_x_kernel(const float* __restrict__ x) {
    size_t i4 = (size_t)blockIdx.x * 256 + threadIdx.x;
    float4 v = reinterpret_cast<const float4*>(x)[i4];
    __half2* o = reinterpret_cast<__half2*>(g_x) + i4 * 2;
    o[0] = __floats2half2_rn(v.x, v.y);
    o[1] = __floats2half2_rn(v.z, v.w);
}

// W [E][D] row-major -> [z][n][k] transposed fp16
__global__ __launch_bounds__(256) void convert_w_kernel(
    const float* __restrict__ Wq, const float* __restrict__ Wk, const float* __restrict__ Wv)
{
    const float* W = (blockIdx.z == 0) ? Wq : (blockIdx.z == 1) ? Wk : Wv;
    __half* o = g_W + (size_t)blockIdx.z * E * D;

    __shared__ float t[32][33];
    const int tx = threadIdx.x & 31, ty = threadIdx.x >> 5;   // 32 x 8
#pragma unroll
    for (int i = 0; i < 4; i++) {
        int kk = blockIdx.y * 32 + ty + i * 8;
        t[ty + i * 8][tx] = W[(size_t)kk * D + blockIdx.x * 32 + tx];
    }
    __syncthreads();
#pragma unroll
    for (int i = 0; i < 4; i++) {
        int n  = blockIdx.x * 32 + ty + i * 8;
        int kk = blockIdx.y * 32 + tx;
        o[(size_t)n * E + kk] = __float2half_rn(t[tx][ty + i * 8]);
    }
}

// ───────────────────────── softmax ───────────────────────────────────
__global__ __launch_bounds__(256) void softmax_kernel() {
    const int b = blockIdx.y, q = blockIdx.x;
    const __half* row = g_sc + ((size_t)b * S + q) * S;
    __half* op = g_p + ((size_t)b * S + q) * S;
    const int tid = threadIdx.x;

    __shared__ float red[256];

    float vals[8];
#pragma unroll
    for (int i = 0; i < 2; i++) {
        // vectorized 8-byte loads: 4 halves each
        const __half2* r2 = reinterpret_cast<const __half2*>(row) + tid * 2 + i * 512;
        float2 p0 = __half22float2(r2[0]);
        float2 p1 = __half22float2(r2[1]);
        vals[i * 4 + 0] = p0.x; vals[i * 4 + 1] = p0.y;
        vals[i * 4 + 2] = p1.x; vals[i * 4 + 3] = p1.y;
    }

    float lmax = -INFINITY;
#pragma unroll
    for (int i = 0; i < 8; i++) lmax = fmaxf(lmax, vals[i]);
    red[tid] = lmax;
    __syncthreads();
    for (int st = 128; st > 0; st >>= 1) {
        if (tid < st) red[tid] = fmaxf(red[tid], red[tid + st]);
        __syncthreads();
    }
    const float mx = red[0];
    __syncthreads();

    float lsum = 0.0f;
#pragma unroll
    for (int i = 0; i < 8; i++) { vals[i] = expf(vals[i] - mx); lsum += vals[i]; }
    red[tid] = lsum;
    __syncthreads();
    for (int st = 128; st > 0; st >>= 1) {
        if (tid < st) red[tid] += red[tid + st];
        __syncthreads();
    }
    const float inv = 1.0f / red[0];

#pragma unroll
    for (int i = 0; i < 2; i++) {
        __half2* o2 = reinterpret_cast<__half2*>(op) + tid * 2 + i * 512;
        o2[0] = __floats2half2_rn(vals[i * 4 + 0] * inv, vals[i * 4 + 1] * inv);
        o2[1] = __floats2half2_rn(vals[i * 4 + 2] * inv, vals[i * 4 + 3] * inv);
    }
}

// ───────────────────────── host launch ───────────────────────────────
extern "C" void kernel_launch(void* const* d_in, const int* in_sizes, int n_in,
                              void* d_out, int out_size)
{
    const float* x    = (const float*)d_in[0];
    const int*   mask = (const int*)  d_in[1];
    const float* Wq   = (const float*)d_in[2];
    const float* bq   = (const float*)d_in[3];
    const float* Wk   = (const float*)d_in[4];
    const float* bk   = (const float*)d_in[5];
    const float* Wv   = (const float*)d_in[6];
    const float* bv   = (const float*)d_in[7];
    float* out = (float*)d_out;

    cudaFuncSetAttribute(gemm_kernel<0>, cudaFuncAttributeMaxDynamicSharedMemorySize, SMEM_TOTAL);
    cudaFuncSetAttribute(gemm_kernel<1>, cudaFuncAttributeMaxDynamicSharedMemorySize, SMEM_TOTAL);
    cudaFuncSetAttribute(gemm_kernel<2>, cudaFuncAttributeMaxDynamicSharedMemorySize, SMEM_TOTAL);
    cudaFuncSetAttribute(gemm_kernel<3>, cudaFuncAttributeMaxDynamicSharedMemorySize, SMEM_TOTAL);
    cudaFuncSetAttribute(gemm_kernel<4>, cudaFuncAttributeMaxDynamicSharedMemorySize, SMEM_TOTAL);

    // 1) fp32 -> fp16
    convert_x_kernel<<<(unsigned)((size_t)Bsz * S * E / 4 / 256), 256>>>(x);
    convert_w_kernel<<<dim3(D / 32, E / 32, 3), 256>>>(Wq, Wk, Wv);

    // 2) projections: Q, K ([token][d]), V (transposed, [b][d][s])
    gemm_kernel<0><<<dim3(D / BN, (Bsz * S) / BM, 1), NTH, SMEM_TOTAL>>>(bq, nullptr, nullptr);
    gemm_kernel<1><<<dim3(D / BN, (Bsz * S) / BM, 1), NTH, SMEM_TOTAL>>>(bk, nullptr, nullptr);
    gemm_kernel<2><<<dim3((Bsz * S) / BN, D / BM, 1), NTH, SMEM_TOTAL>>>(bv, nullptr, nullptr);

    // 3) scores = QK^T / 1024, masked (fp16 scratch)
    gemm_kernel<3><<<dim3(S / BN, S / BM, Bsz), NTH, SMEM_TOTAL>>>(nullptr, mask, nullptr);

    // 4) softmax -> fp16 probs
    softmax_kernel<<<dim3(S, Bsz), 256>>>();

    // 5) out = P @ V
    gemm_kernel<4><<<dim3(D / BN, S / BM, Bsz), NTH, SMEM_TOTAL>>>(nullptr, nullptr, out);
}

// round 9
// speedup vs baseline: 2.9439x; 1.1408x over previous
#include <cuda_runtime.h>
#include <cuda_fp16.h>
#include <cstdint>
#include <math.h>

// ───────────────────────── problem constants ─────────────────────────
constexpr int Bsz = 4, S = 2048, E = 1024, D = 1024;

// All fp16 operand scratch lives in "tiled-swizzled image" format:
//   operand viewed as rows r (M or N dim) × k;  tile (rb, kb) = 128 rows × 64 k,
//   16KB contiguous at (rb * NKB + kb) * 16384 bytes, NKB = K/64.
//   within tile: element (ir, ik) at byte  ir*128 + ((ik*2) ^ ((ir&7)<<4)).
__device__ __half g_x[(size_t)Bsz * S * E];      // rows=token, k=e     (NKB 16)
__device__ __half g_W[(size_t)3 * E * D];        // per z: rows=n, k=e  (NKB 16)
__device__ __half g_q[(size_t)Bsz * S * D];      // rows=token, k=d    (NKB 16)
__device__ __half g_k[(size_t)Bsz * S * D];      // rows=token, k=d    (NKB 16)
__device__ __half g_v[(size_t)Bsz * D * S];      // per b: rows=d, k=s (NKB 32)
__device__ __half g_sc[(size_t)Bsz * S * S];     // per b: rows=q, k=key (NKB 32)
__device__ __half g_p[(size_t)Bsz * S * S];      // probs, same layout

__device__ __forceinline__ __half* img_addr(__half* base, int r, int k, int nkb) {
    size_t tile = (size_t)((r >> 7) * nkb + (k >> 6));
    uint32_t off = (uint32_t)((r & 127) * 128) +
                   ((((uint32_t)(k & 63)) * 2) ^ (((uint32_t)r & 7) << 4));
    return (__half*)((char*)base + (tile << 14) + off);
}

// ───────────────────────── tile config ───────────────────────────────
constexpr int BM = 128, BN = 128, BK = 64, NTH = 256, NSTAGE = 3;
constexpr int TILE_B = 16384;                  // 128 x 64 halfs
constexpr int STAGE_B = 2 * TILE_B;            // A, B
constexpr int SMEM_MBAR = NSTAGE * STAGE_B;    // 98304
constexpr int SMEM_TOTAL = SMEM_MBAR + 64;

// ───────────────────────── PTX helpers ───────────────────────────────
__device__ __forceinline__ uint32_t s2u(const void* p) {
    uint32_t a;
    asm("{ .reg .u64 t; cvta.to.shared.u64 t, %1; cvt.u32.u64 %0, t; }" : "=r"(a) : "l"(p));
    return a;
}
__device__ __forceinline__ void mbar_init(uint32_t addr, uint32_t cnt) {
    asm volatile("mbarrier.init.shared.b64 [%0], %1;" :: "r"(addr), "r"(cnt) : "memory");
}
__device__ __forceinline__ void mbar_expect_tx(uint32_t addr, uint32_t bytes) {
    asm volatile("mbarrier.arrive.expect_tx.shared::cta.b64 _, [%0], %1;"
                 :: "r"(addr), "r"(bytes) : "memory");
}
__device__ __forceinline__ void mbar_wait(uint32_t addr, uint32_t parity) {
    asm volatile(
        "{\n\t.reg .pred P;\n\t"
        "WL_%=:\n\t"
        "mbarrier.try_wait.parity.acquire.cta.shared::cta.b64 P, [%0], %1, 0x989680;\n\t"
        "@!P bra WL_%=;\n\t}"
        :: "r"(addr), "r"(parity) : "memory");
}
__device__ __forceinline__ void bulk_g2s(uint32_t sdst, const void* gsrc, uint32_t bytes,
                                         uint32_t mbar) {
    asm volatile(
        "cp.async.bulk.shared::cluster.global.mbarrier::complete_tx::bytes "
        "[%0], [%1], %2, [%3];"
        :: "r"(sdst), "l"(gsrc), "r"(bytes), "r"(mbar) : "memory");
}
__device__ __forceinline__ void ldmatrix4(uint32_t* r, uint32_t addr) {
    asm volatile("ldmatrix.sync.aligned.m8n8.x4.shared.b16 {%0,%1,%2,%3}, [%4];"
                 : "=r"(r[0]), "=r"(r[1]), "=r"(r[2]), "=r"(r[3]) : "r"(addr));
}
__device__ __forceinline__ void mma16816(float* c, const uint32_t* a, const uint32_t* b) {
    asm volatile(
        "mma.sync.aligned.m16n8k16.row.col.f32.f16.f16.f32 "
        "{%0,%1,%2,%3}, {%4,%5,%6,%7}, {%8,%9}, {%0,%1,%2,%3};"
        : "+f"(c[0]), "+f"(c[1]), "+f"(c[2]), "+f"(c[3])
        : "r"(a[0]), "r"(a[1]), "r"(a[2]), "r"(a[3]), "r"(b[0]), "r"(b[1]));
}

// ───────────────────────── GEMM ──────────────────────────────────────
// C[m][n] = sum_k A[m][k]*B[n][k]; both operands in tiled-swizzled image form.
// OP: 0=Q proj, 1=K proj, 2=V proj (transposed out), 3=scores, 4=PV
template <int OP>
__global__ __launch_bounds__(NTH, 2) void gemm_kernel(
    const float* __restrict__ bias,
    const int*   __restrict__ mask,
    float*       __restrict__ outF)
{
    extern __shared__ char smem[];
    const uint32_t sbase = s2u(smem);
    const int tid = threadIdx.x;
    const int wid = tid >> 5, lane = tid & 31;
    const size_t z = blockIdx.z;

    const char* Aimg;
    const char* Bimg;
    int NKB;
    if (OP == 0)      { Aimg = (const char*)g_x; Bimg = (const char*)g_W; NKB = 16; }
    else if (OP == 1) { Aimg = (const char*)g_x; Bimg = (const char*)(g_W + (size_t)E * D); NKB = 16; }
    else if (OP == 2) { Aimg = (const char*)(g_W + (size_t)2 * E * D); Bimg = (const char*)g_x; NKB = 16; }
    else if (OP == 3) { Aimg = (const char*)(g_q + z * (size_t)S * D);
                        Bimg = (const char*)(g_k + z * (size_t)S * D); NKB = 16; }
    else              { Aimg = (const char*)(g_p + z * (size_t)S * S);
                        Bimg = (const char*)(g_v + z * (size_t)D * S); NKB = 32; }

    const int by = blockIdx.y, bx = blockIdx.x;
    const int NC = NKB;   // K/64

    // mbarrier init
    const uint32_t mb0 = sbase + SMEM_MBAR;
    if (tid == 0) {
        mbar_init(mb0, 1); mbar_init(mb0 + 8, 1); mbar_init(mb0 + 16, 1);
    }
    __syncthreads();

    auto issue_load = [&](int c) {
        const int st = c % NSTAGE;
        const uint32_t mb = mb0 + 8u * st;
        mbar_expect_tx(mb, 2 * TILE_B);
        bulk_g2s(sbase + st * STAGE_B,
                 Aimg + (((size_t)by * NKB + c) << 14), TILE_B, mb);
        bulk_g2s(sbase + st * STAGE_B + TILE_B,
                 Bimg + (((size_t)bx * NKB + c) << 14), TILE_B, mb);
    };

    if (tid == 0) { issue_load(0); issue_load(1); }

    float acc[2][8][4];
#pragma unroll
    for (int i = 0; i < 2; i++)
#pragma unroll
        for (int j = 0; j < 8; j++)
#pragma unroll
            for (int t = 0; t < 4; t++) acc[i][j][t] = 0.0f;

    const int wm = (wid & 3) * 32;    // 4 warps in m
    const int wn = (wid >> 2) * 64;   // 2 warps in n

    // per-lane ldmatrix row components (swizzle: addr = r*128 + (koff ^ ((r&7)<<4)))
    const int aR  = wm + (lane & 15);
    const int aK0 = (lane >> 4) * 16;
    const int bR  = wn + (lane & 7) + ((lane >> 4) << 3);
    const int bK0 = ((lane >> 3) & 1) * 16;

    for (int c = 0; c < NC; c++) {
        const int st = c % NSTAGE;
        mbar_wait(mb0 + 8u * st, (c / NSTAGE) & 1);

        const uint32_t sA = sbase + st * STAGE_B;
        const uint32_t sB = sA + TILE_B;

#pragma unroll
        for (int ks = 0; ks < 4; ks++) {
            uint32_t a[2][4], b[4][4];
#pragma unroll
            for (int i = 0; i < 2; i++) {
                const int r = aR + i * 16;
                ldmatrix4(a[i], sA + r * 128 + ((ks * 32 + aK0) ^ ((r & 7) << 4)));
            }
#pragma unroll
            for (int j = 0; j < 4; j++) {
                const int r = bR + j * 16;
                ldmatrix4(b[j], sB + r * 128 + ((ks * 32 + bK0) ^ ((r & 7) << 4)));
            }
#pragma unroll
            for (int i = 0; i < 2; i++)
#pragma unroll
                for (int j = 0; j < 4; j++) {
                    mma16816(acc[i][2 * j],     a[i], &b[j][0]);
                    mma16816(acc[i][2 * j + 1], a[i], &b[j][2]);
                }
        }

        __syncthreads();                       // all warps done reading stage st
        if (tid == 0 && c + 2 < NC) issue_load(c + 2);
    }

    // ───────── epilogue ─────────
    __half* oH = nullptr;
    if (OP == 0) oH = g_q;
    else if (OP == 1) oH = g_k;
    else if (OP == 2) oH = g_v;

    const int row0 = by * BM, col0 = bx * BN;

#pragma unroll
    for (int i = 0; i < 2; i++) {
        const int m = row0 + wm + i * 16 + (lane >> 2);
        float bm0 = 0.0f, bm1 = 0.0f;
        if (OP == 2) { bm0 = bias[m]; bm1 = bias[m + 8]; }
#pragma unroll
        for (int j = 0; j < 8; j++) {
            const int n = col0 + wn + j * 8 + 2 * (lane & 3);
            float v00 = acc[i][j][0], v01 = acc[i][j][1];   // row m
            float v10 = acc[i][j][2], v11 = acc[i][j][3];   // row m+8

            if (OP == 0 || OP == 1) {
                // image: rows=token(m), k=d(n), NKB=16
                float2 bb = *reinterpret_cast<const float2*>(bias + n);
                *reinterpret_cast<__half2*>(img_addr(oH, m, n, 16)) =
                    __floats2half2_rn(v00 + bb.x, v01 + bb.y);
                *reinterpret_cast<__half2*>(img_addr(oH, m + 8, n, 16)) =
                    __floats2half2_rn(v10 + bb.x, v11 + bb.y);
            } else if (OP == 2) {
                // m = d, n = global token: per-batch image rows=d, k=s, NKB=32
                const int b = n >> 11, sI = n & 2047;
                __half* base = oH + (size_t)b * D * S;
                *reinterpret_cast<__half2*>(img_addr(base, m, sI, 32)) =
                    __floats2half2_rn(v00 + bm0, v01 + bm0);
                *reinterpret_cast<__half2*>(img_addr(base, m + 8, sI, 32)) =
                    __floats2half2_rn(v10 + bm1, v11 + bm1);
            } else if (OP == 3) {
                const float sc = 1.0f / 1024.0f;
                const int* mrow = mask + z * (size_t)S * S;
                __half* base = g_sc + z * (size_t)S * S;  // rows=q, k=key, NKB=32
                int2 mk = *reinterpret_cast<const int2*>(mrow + (size_t)m * S + n);
                *reinterpret_cast<__half2*>(img_addr(base, m, n, 32)) =
                    __floats2half2_rn(mk.x == 0 ? -INFINITY : v00 * sc,
                                      mk.y == 0 ? -INFINITY : v01 * sc);
                mk = *reinterpret_cast<const int2*>(mrow + (size_t)(m + 8) * S + n);
                *reinterpret_cast<__half2*>(img_addr(base, m + 8, n, 32)) =
                    __floats2half2_rn(mk.x == 0 ? -INFINITY : v10 * sc,
                                      mk.y == 0 ? -INFINITY : v11 * sc);
            } else {
                float* O = outF + z * (size_t)S * D;
                float2 o;
                o.x = v00; o.y = v01;
                *reinterpret_cast<float2*>(O + (size_t)m * D + n) = o;
                o.x = v10; o.y = v11;
                *reinterpret_cast<float2*>(O + (size_t)(m + 8) * D + n) = o;
            }
        }
    }
}

// ───────────────────────── conversion kernels ────────────────────────
// x fp32 [8192][1024] -> tiled image (rows=token, k=e, NKB=16)
__global__ __launch_bounds__(256) void convert_x_kernel(const float* __restrict__ x) {
    const uint32_t uid = blockIdx.x * 256 + threadIdx.x;   // one 16B unit (8 k)
    const int r = uid >> 7;            // token row
    const int u7 = uid & 127;          // unit within row (k = u7*8)
    const int k = u7 * 8;
    const float4* src = reinterpret_cast<const float4*>(x + (size_t)r * E + k);
    float4 v0 = src[0], v1 = src[1];
    __half2 h[4];
    h[0] = __floats2half2_rn(v0.x, v0.y);
    h[1] = __floats2half2_rn(v0.z, v0.w);
    h[2] = __floats2half2_rn(v1.x, v1.y);
    h[3] = __floats2half2_rn(v1.z, v1.w);
    *reinterpret_cast<uint4*>(img_addr(g_x, r, k, 16)) = *reinterpret_cast<uint4*>(h);
}

// W [E][D] fp32 -> per z image (rows=n, k=e, NKB=16)
__global__ __launch_bounds__(256) void convert_w_kernel(
    const float* __restrict__ Wq, const float* __restrict__ Wk, const float* __restrict__ Wv)
{
    const float* W = (blockIdx.z == 0) ? Wq : (blockIdx.z == 1) ? Wk : Wv;
    __half* o = g_W + (size_t)blockIdx.z * E * D;

    __shared__ float t[32][33];       // t[e_local][n_local]
    const int tx = threadIdx.x & 31, ty = threadIdx.x >> 5;   // 32 x 8
    const int nb = blockIdx.x * 32, eb = blockIdx.y * 32;
#pragma unroll
    for (int i = 0; i < 4; i++) {
        int e = eb + ty + i * 8;
        t[ty + i * 8][tx] = W[(size_t)e * D + nb + tx];
    }
    __syncthreads();
#pragma unroll
    for (int j = 0; j < 2; j++) {
        const int idx = j * 256 + threadIdx.x;    // 0..511
        const int nl = idx & 31, ep = idx >> 5;   // 16 e-pairs
        const int n = nb + nl, e = eb + ep * 2;
        *reinterpret_cast<__half2*>(img_addr(o, n, e, 16)) =
            __floats2half2_rn(t[ep * 2][nl], t[ep * 2 + 1][nl]);
    }
}

// ───────────────────────── softmax (tiled-image in/out) ──────────────
__global__ __launch_bounds__(256) void softmax_kernel() {
    const int b = blockIdx.y, q = blockIdx.x;
    const char* ibase = (const char*)(g_sc + (size_t)b * S * S);
    char* obase = (char*)(g_p + (size_t)b * S * S);
    const int tid = threadIdx.x;

    const int rb = q >> 7, ir = q & 127;
    const int kb = tid >> 3, u = tid & 7;      // tile 0..31, 16B unit 0..7
    const size_t off = ((size_t)(rb * 32 + kb) << 14) +
                       (uint32_t)(ir * 128) + ((u * 16) ^ ((ir & 7) << 4));

    __half2 hv[4];
    *reinterpret_cast<uint4*>(hv) = *reinterpret_cast<const uint4*>(ibase + off);
    float vals[8];
#pragma unroll
    for (int i = 0; i < 4; i++) {
        float2 f = __half22float2(hv[i]);
        vals[2 * i] = f.x; vals[2 * i + 1] = f.y;
    }

    __shared__ float red[256];
    float lmax = -INFINITY;
#pragma unroll
    for (int i = 0; i < 8; i++) lmax = fmaxf(lmax, vals[i]);
    red[tid] = lmax;
    __syncthreads();
    for (int st = 128; st > 0; st >>= 1) {
        if (tid < st) red[tid] = fmaxf(red[tid], red[tid + st]);
        __syncthreads();
    }
    const float mx = red[0];
    __syncthreads();

    float lsum = 0.0f;
#pragma unroll
    for (int i = 0; i < 8; i++) { vals[i] = expf(vals[i] - mx); lsum += vals[i]; }
    red[tid] = lsum;
    __syncthreads();
    for (int st = 128; st > 0; st >>= 1) {
        if (tid < st) red[tid] += red[tid + st];
        __syncthreads();
    }
    const float inv = 1.0f / red[0];

#pragma unroll
    for (int i = 0; i < 4; i++)
        hv[i] = __floats2half2_rn(vals[2 * i] * inv, vals[2 * i + 1] * inv);
    *reinterpret_cast<uint4*>(obase + off) = *reinterpret_cast<uint4*>(hv);
}

// ───────────────────────── host launch ───────────────────────────────
extern "C" void kernel_launch(void* const* d_in, const int* in_sizes, int n_in,
                              void* d_out, int out_size)
{
    const float* x    = (const float*)d_in[0];
    const int*   mask = (const int*)  d_in[1];
    const float* Wq   = (const float*)d_in[2];
    const float* bq   = (const float*)d_in[3];
    const float* Wk   = (const float*)d_in[4];
    const float* bk   = (const float*)d_in[5];
    const float* Wv   = (const float*)d_in[6];
    const float* bv   = (const float*)d_in[7];
    float* out = (float*)d_out;

    cudaFuncSetAttribute(gemm_kernel<0>, cudaFuncAttributeMaxDynamicSharedMemorySize, SMEM_TOTAL);
    cudaFuncSetAttribute(gemm_kernel<1>, cudaFuncAttributeMaxDynamicSharedMemorySize, SMEM_TOTAL);
    cudaFuncSetAttribute(gemm_kernel<2>, cudaFuncAttributeMaxDynamicSharedMemorySize, SMEM_TOTAL);
    cudaFuncSetAttribute(gemm_kernel<3>, cudaFuncAttributeMaxDynamicSharedMemorySize, SMEM_TOTAL);
    cudaFuncSetAttribute(gemm_kernel<4>, cudaFuncAttributeMaxDynamicSharedMemorySize, SMEM_TOTAL);

    // 1) fp32 -> fp16 tiled-swizzled images
    convert_x_kernel<<<(unsigned)((size_t)Bsz * S * E / 8 / 256), 256>>>(x);
    convert_w_kernel<<<dim3(D / 32, E / 32, 3), 256>>>(Wq, Wk, Wv);

    // 2) projections: Q, K (rows=token), V (rows=d, per-batch transposed)
    gemm_kernel<0><<<dim3(D / BN, (Bsz * S) / BM, 1), NTH, SMEM_TOTAL>>>(bq, nullptr, nullptr);
    gemm_kernel<1><<<dim3(D / BN, (Bsz * S) / BM, 1), NTH, SMEM_TOTAL>>>(bk, nullptr, nullptr);
    gemm_kernel<2><<<dim3((Bsz * S) / BN, D / BM, 1), NTH, SMEM_TOTAL>>>(bv, nullptr, nullptr);

    // 3) scores = QK^T / 1024, masked (tiled fp16 scratch)
    gemm_kernel<3><<<dim3(S / BN, S / BM, Bsz), NTH, SMEM_TOTAL>>>(nullptr, mask, nullptr);

    // 4) softmax -> tiled fp16 probs
    softmax_kernel<<<dim3(S, Bsz), 256>>>();

    // 5) out = P @ V
    gemm_kernel<4><<<dim3(D / BN, S / BM, Bsz), NTH, SMEM_TOTAL>>>(nullptr, nullptr, out);
}

// round 10
// speedup vs baseline: 3.4119x; 1.1590x over previous
#include <cuda_runtime.h>
#include <cuda_fp16.h>
#include <cstdint>
#include <math.h>

// ───────────────────────── problem constants ─────────────────────────
constexpr int Bsz = 4, S = 2048, E = 1024, D = 1024;

// Tiled-swizzled image format for all fp16 operands:
//   tile (rb, kb) = 128 rows × 64 k = 16KB contiguous at (rb*NKB + kb)*16384,
//   element (ir, ik) at byte ir*128 + ((ik*2) ^ ((ir&7)<<4)).
__device__ __half g_x[(size_t)Bsz * S * E];      // rows=token, k=e   (NKB 16)
__device__ __half g_W[(size_t)3 * E * D];        // per z: rows=n, k=e (NKB 16)
__device__ __half g_q[(size_t)Bsz * S * D];      // rows=token, k=d   (NKB 16)
__device__ __half g_k[(size_t)Bsz * S * D];      // rows=token, k=d   (NKB 16)
__device__ __half g_v[(size_t)Bsz * D * S];      // per b: rows=d, k=s (NKB 32)
__device__ __half g_p[(size_t)Bsz * S * S];      // exp'd unnormalized probs (NKB 32)
__device__ float  g_rs[(size_t)Bsz * S * 32];    // per-row partial sums (32 slots)

__device__ __forceinline__ __half* img_addr(__half* base, int r, int k, int nkb) {
    size_t tile = (size_t)((r >> 7) * nkb + (k >> 6));
    uint32_t off = (uint32_t)((r & 127) * 128) +
                   ((((uint32_t)(k & 63)) * 2) ^ (((uint32_t)r & 7) << 4));
    return (__half*)((char*)base + (tile << 14) + off);
}

// ───────────────────────── tile config ───────────────────────────────
constexpr int NTH = 256;
constexpr int TILE_B = 16384;                  // 128 x 64 halfs
constexpr int STAGE_B = 2 * TILE_B;            // A, B
constexpr int SMEM_MBAR = 3 * STAGE_B;         // 98304
constexpr int SMEM_TOTAL = SMEM_MBAR + 64;

// ───────────────────────── PTX helpers ───────────────────────────────
__device__ __forceinline__ uint32_t s2u(const void* p) {
    uint32_t a;
    asm("{ .reg .u64 t; cvta.to.shared.u64 t, %1; cvt.u32.u64 %0, t; }" : "=r"(a) : "l"(p));
    return a;
}
__device__ __forceinline__ void mbar_init(uint32_t addr, uint32_t cnt) {
    asm volatile("mbarrier.init.shared.b64 [%0], %1;" :: "r"(addr), "r"(cnt) : "memory");
}
__device__ __forceinline__ void mbar_expect_tx(uint32_t addr, uint32_t bytes) {
    asm volatile("mbarrier.arrive.expect_tx.shared::cta.b64 _, [%0], %1;"
                 :: "r"(addr), "r"(bytes) : "memory");
}
__device__ __forceinline__ void mbar_wait(uint32_t addr, uint32_t parity) {
    asm volatile(
        "{\n\t.reg .pred P;\n\t"
        "WL_%=:\n\t"
        "mbarrier.try_wait.parity.acquire.cta.shared::cta.b64 P, [%0], %1, 0x989680;\n\t"
        "@!P bra WL_%=;\n\t}"
        :: "r"(addr), "r"(parity) : "memory");
}
__device__ __forceinline__ void bulk_g2s(uint32_t sdst, const void* gsrc, uint32_t bytes,
                                         uint32_t mbar) {
    asm volatile(
        "cp.async.bulk.shared::cluster.global.mbarrier::complete_tx::bytes "
        "[%0], [%1], %2, [%3];"
        :: "r"(sdst), "l"(gsrc), "r"(bytes), "r"(mbar) : "memory");
}
__device__ __forceinline__ void ldmatrix4(uint32_t* r, uint32_t addr) {
    asm volatile("ldmatrix.sync.aligned.m8n8.x4.shared.b16 {%0,%1,%2,%3}, [%4];"
                 : "=r"(r[0]), "=r"(r[1]), "=r"(r[2]), "=r"(r[3]) : "r"(addr));
}
__device__ __forceinline__ void mma16816(float* c, const uint32_t* a, const uint32_t* b) {
    asm volatile(
        "mma.sync.aligned.m16n8k16.row.col.f32.f16.f16.f32 "
        "{%0,%1,%2,%3}, {%4,%5,%6,%7}, {%8,%9}, {%0,%1,%2,%3};"
        : "+f"(c[0]), "+f"(c[1]), "+f"(c[2]), "+f"(c[3])
        : "r"(a[0]), "r"(a[1]), "r"(a[2]), "r"(a[3]), "r"(b[0]), "r"(b[1]));
}

// ───────────────────────── shared GEMM core ──────────────────────────
// acc[2][8][4]: warp tile 32x64 (4 warps m, 2 warps n), CTA 128x128, BK=64.
__device__ __forceinline__ void gemm_core(
    uint32_t sbase, const char* Aimg, const char* Bimg,
    int by, int bx, int NC,
    float (&acc)[2][8][4], int tid, int wid, int lane)
{
    const uint32_t mb0 = sbase + SMEM_MBAR;
    if (tid == 0) { mbar_init(mb0, 1); mbar_init(mb0 + 8, 1); mbar_init(mb0 + 16, 1); }
    __syncthreads();

    auto issue_load = [&](int c) {
        const int st = c % 3;
        const uint32_t mb = mb0 + 8u * st;
        mbar_expect_tx(mb, 2 * TILE_B);
        bulk_g2s(sbase + st * STAGE_B, Aimg + (((size_t)by * NC + c) << 14), TILE_B, mb);
        bulk_g2s(sbase + st * STAGE_B + TILE_B, Bimg + (((size_t)bx * NC + c) << 14), TILE_B, mb);
    };
    if (tid == 0) { issue_load(0); issue_load(1); }

    const int wm = (wid & 3) * 32;
    const int wn = (wid >> 2) * 64;
    const int aR  = wm + (lane & 15);
    const int aK0 = (lane >> 4) * 16;
    const int bR  = wn + (lane & 7) + ((lane >> 4) << 3);
    const int bK0 = ((lane >> 3) & 1) * 16;

    for (int c = 0; c < NC; c++) {
        const int st = c % 3;
        mbar_wait(mb0 + 8u * st, (c / 3) & 1);
        __syncthreads();                          // all warps done with stage (c-1)%3
        if (tid == 0 && c + 2 < NC) issue_load(c + 2);

        const uint32_t sA = sbase + st * STAGE_B;
        const uint32_t sB = sA + TILE_B;

#pragma unroll
        for (int ks = 0; ks < 4; ks++) {
            uint32_t a[2][4], b[4][4];
#pragma unroll
            for (int i = 0; i < 2; i++) {
                const int r = aR + i * 16;
                ldmatrix4(a[i], sA + r * 128 + ((ks * 32 + aK0) ^ ((r & 7) << 4)));
            }
#pragma unroll
            for (int j = 0; j < 4; j++) {
                const int r = bR + j * 16;
                ldmatrix4(b[j], sB + r * 128 + ((ks * 32 + bK0) ^ ((r & 7) << 4)));
            }
#pragma unroll
            for (int i = 0; i < 2; i++)
#pragma unroll
                for (int j = 0; j < 4; j++) {
                    mma16816(acc[i][2 * j],     a[i], &b[j][0]);
                    mma16816(acc[i][2 * j + 1], a[i], &b[j][2]);
                }
        }
    }
}

// ───────────────────────── QKV projection kernel ─────────────────────
// grid (512, 3): z=0 Q, z=1 K (rows=token), z=2 V (rows=d, transposed out).
__global__ __launch_bounds__(NTH, 2) void qkv_kernel(
    const float* __restrict__ bq, const float* __restrict__ bk, const float* __restrict__ bv)
{
    extern __shared__ char smem[];
    const uint32_t sbase = s2u(smem);
    const int tid = threadIdx.x, wid = tid >> 5, lane = tid & 31;
    const int z = blockIdx.y, idx = blockIdx.x;

    int by, bx;
    const char *Aimg, *Bimg;
    if (z < 2) { by = idx >> 3; bx = idx & 7; Aimg = (const char*)g_x;
                 Bimg = (const char*)(g_W + (size_t)z * E * D); }
    else       { by = idx & 7; bx = idx >> 3; Aimg = (const char*)(g_W + (size_t)2 * E * D);
                 Bimg = (const char*)g_x; }

    float acc[2][8][4];
#pragma unroll
    for (int i = 0; i < 2; i++)
#pragma unroll
        for (int j = 0; j < 8; j++)
#pragma unroll
            for (int t = 0; t < 4; t++) acc[i][j][t] = 0.0f;

    gemm_core(sbase, Aimg, Bimg, by, bx, 16, acc, tid, wid, lane);

    const int wm = (wid & 3) * 32, wn = (wid >> 2) * 64;
    const int row0 = by * 128, col0 = bx * 128;

    if (z < 2) {
        const float* bias = z ? bk : bq;
        __half* oH = z ? g_k : g_q;
#pragma unroll
        for (int i = 0; i < 2; i++) {
            const int m = row0 + wm + i * 16 + (lane >> 2);
#pragma unroll
            for (int j = 0; j < 8; j++) {
                const int n = col0 + wn + j * 8 + 2 * (lane & 3);
                float2 bb = *reinterpret_cast<const float2*>(bias + n);
                *reinterpret_cast<__half2*>(img_addr(oH, m, n, 16)) =
                    __floats2half2_rn(acc[i][j][0] + bb.x, acc[i][j][1] + bb.y);
                *reinterpret_cast<__half2*>(img_addr(oH, m + 8, n, 16)) =
                    __floats2half2_rn(acc[i][j][2] + bb.x, acc[i][j][3] + bb.y);
            }
        }
    } else {
#pragma unroll
        for (int i = 0; i < 2; i++) {
            const int m = row0 + wm + i * 16 + (lane >> 2);   // d index
            const float bm0 = bv[m], bm1 = bv[m + 8];
#pragma unroll
            for (int j = 0; j < 8; j++) {
                const int n = col0 + wn + j * 8 + 2 * (lane & 3);  // global token
                const int b = n >> 11, sI = n & 2047;
                __half* base = g_v + (size_t)b * D * S;
                *reinterpret_cast<__half2*>(img_addr(base, m, sI, 32)) =
                    __floats2half2_rn(acc[i][j][0] + bm0, acc[i][j][1] + bm0);
                *reinterpret_cast<__half2*>(img_addr(base, m + 8, sI, 32)) =
                    __floats2half2_rn(acc[i][j][2] + bm1, acc[i][j][3] + bm1);
            }
        }
    }
}

// ───────────────────────── scores kernel ─────────────────────────────
// p' = mask ? exp(q·k/1024) : 0  (fp16, unnormalized) + per-row partial sums.
__global__ __launch_bounds__(NTH, 2) void scores_kernel(const int* __restrict__ mask)
{
    extern __shared__ char smem[];
    const uint32_t sbase = s2u(smem);
    const int tid = threadIdx.x, wid = tid >> 5, lane = tid & 31;
    const size_t z = blockIdx.z;
    const int by = blockIdx.y, bx = blockIdx.x;

    float acc[2][8][4];
#pragma unroll
    for (int i = 0; i < 2; i++)
#pragma unroll
        for (int j = 0; j < 8; j++)
#pragma unroll
            for (int t = 0; t < 4; t++) acc[i][j][t] = 0.0f;

    gemm_core(sbase, (const char*)(g_q + z * (size_t)S * D),
              (const char*)(g_k + z * (size_t)S * D), by, bx, 16, acc, tid, wid, lane);

    const int wm = (wid & 3) * 32, wn = (wid >> 2) * 64;
    const int row0 = by * 128, col0 = bx * 128;
    const float sc = 1.0f / 1024.0f;
    const int* mbase = mask + z * (size_t)S * S;
    __half* pbase = g_p + z * (size_t)S * S;
    float* rs = g_rs + z * (size_t)S * 32;
    const int slot = bx * 2 + (wid >> 2);

#pragma unroll
    for (int i = 0; i < 2; i++) {
        const int m = row0 + wm + i * 16 + (lane >> 2);
        float s0 = 0.0f, s1 = 0.0f;
#pragma unroll
        for (int j = 0; j < 8; j++) {
            const int n = col0 + wn + j * 8 + 2 * (lane & 3);
            int2 mk = *reinterpret_cast<const int2*>(mbase + (size_t)m * S + n);
            float p00 = mk.x ? __expf(acc[i][j][0] * sc) : 0.0f;
            float p01 = mk.y ? __expf(acc[i][j][1] * sc) : 0.0f;
            mk = *reinterpret_cast<const int2*>(mbase + (size_t)(m + 8) * S + n);
            float p10 = mk.x ? __expf(acc[i][j][2] * sc) : 0.0f;
            float p11 = mk.y ? __expf(acc[i][j][3] * sc) : 0.0f;
            *reinterpret_cast<__half2*>(img_addr(pbase, m, n, 32))     = __floats2half2_rn(p00, p01);
            *reinterpret_cast<__half2*>(img_addr(pbase, m + 8, n, 32)) = __floats2half2_rn(p10, p11);
            s0 += p00 + p01;
            s1 += p10 + p11;
        }
        // reduce across the 4 lanes of each quad (same row, different cols)
        s0 += __shfl_xor_sync(0xFFFFFFFF, s0, 1);
        s0 += __shfl_xor_sync(0xFFFFFFFF, s0, 2);
        s1 += __shfl_xor_sync(0xFFFFFFFF, s1, 1);
        s1 += __shfl_xor_sync(0xFFFFFFFF, s1, 2);
        if ((lane & 3) == 0) {
            rs[(size_t)m * 32 + slot]       = s0;
            rs[(size_t)(m + 8) * 32 + slot] = s1;
        }
    }
}

// ───────────────────────── PV kernel ─────────────────────────────────
// out = (P' @ V) / rowsum.
__global__ __launch_bounds__(NTH, 2) void pv_kernel(float* __restrict__ outF)
{
    extern __shared__ char smem[];
    __shared__ float s_inv[128];
    const uint32_t sbase = s2u(smem);
    const int tid = threadIdx.x, wid = tid >> 5, lane = tid & 31;
    const size_t z = blockIdx.z;
    const int by = blockIdx.y, bx = blockIdx.x;

    // row-sum reduction (overlaps with first bulk loads; gemm_core's first
    // __syncthreads makes it visible before the epilogue).
    if (tid < 128) {
        const float* p = g_rs + (z * (size_t)S + by * 128 + tid) * 32;
        float s = 0.0f;
#pragma unroll
        for (int k = 0; k < 32; k++) s += p[k];
        s_inv[tid] = 1.0f / s;
    }

    float acc[2][8][4];
#pragma unroll
    for (int i = 0; i < 2; i++)
#pragma unroll
        for (int j = 0; j < 8; j++)
#pragma unroll
            for (int t = 0; t < 4; t++) acc[i][j][t] = 0.0f;

    gemm_core(sbase, (const char*)(g_p + z * (size_t)S * S),
              (const char*)(g_v + z * (size_t)D * S), by, bx, 32, acc, tid, wid, lane);

    const int wm = (wid & 3) * 32, wn = (wid >> 2) * 64;
    const int row0 = by * 128, col0 = bx * 128;
    float* O = outF + z * (size_t)S * D;

#pragma unroll
    for (int i = 0; i < 2; i++) {
        const int ml = wm + i * 16 + (lane >> 2);
        const int m = row0 + ml;
        const float inv0 = s_inv[ml], inv1 = s_inv[ml + 8];
#pragma unroll
        for (int j = 0; j < 8; j++) {
            const int n = col0 + wn + j * 8 + 2 * (lane & 3);
            float2 o;
            o.x = acc[i][j][0] * inv0; o.y = acc[i][j][1] * inv0;
            *reinterpret_cast<float2*>(O + (size_t)m * D + n) = o;
            o.x = acc[i][j][2] * inv1; o.y = acc[i][j][3] * inv1;
            *reinterpret_cast<float2*>(O + (size_t)(m + 8) * D + n) = o;
        }
    }
}

// ───────────────────────── conversion kernels ────────────────────────
__global__ __launch_bounds__(256) void convert_x_kernel(const float* __restrict__ x) {
    const uint32_t uid = blockIdx.x * 256 + threadIdx.x;   // one 16B unit (8 k)
    const int r = uid >> 7;
    const int k = (uid & 127) * 8;
    const float4* src = reinterpret_cast<const float4*>(x + (size_t)r * E + k);
    float4 v0 = src[0], v1 = src[1];
    __half2 h[4];
    h[0] = __floats2half2_rn(v0.x, v0.y);
    h[1] = __floats2half2_rn(v0.z, v0.w);
    h[2] = __floats2half2_rn(v1.x, v1.y);
    h[3] = __floats2half2_rn(v1.z, v1.w);
    *reinterpret_cast<uint4*>(img_addr(g_x, r, k, 16)) = *reinterpret_cast<uint4*>(h);
}

__global__ __launch_bounds__(256) void convert_w_kernel(
    const float* __restrict__ Wq, const float* __restrict__ Wk, const float* __restrict__ Wv)
{
    const float* W = (blockIdx.z == 0) ? Wq : (blockIdx.z == 1) ? Wk : Wv;
    __half* o = g_W + (size_t)blockIdx.z * E * D;

    __shared__ float t[32][33];       // t[e_local][n_local]
    const int tx = threadIdx.x & 31, ty = threadIdx.x >> 5;
    const int nb = blockIdx.x * 32, eb = blockIdx.y * 32;
#pragma unroll
    for (int i = 0; i < 4; i++) {
        int e = eb + ty + i * 8;
        t[ty + i * 8][tx] = W[(size_t)e * D + nb + tx];
    }
    __syncthreads();
#pragma unroll
    for (int j = 0; j < 2; j++) {
        const int idx = j * 256 + threadIdx.x;
        const int nl = idx & 31, ep = idx >> 5;
        const int n = nb + nl, e = eb + ep * 2;
        *reinterpret_cast<__half2*>(img_addr(o, n, e, 16)) =
            __floats2half2_rn(t[ep * 2][nl], t[ep * 2 + 1][nl]);
    }
}

// ───────────────────────── host launch ───────────────────────────────
extern "C" void kernel_launch(void* const* d_in, const int* in_sizes, int n_in,
                              void* d_out, int out_size)
{
    const float* x    = (const float*)d_in[0];
    const int*   mask = (const int*)  d_in[1];
    const float* Wq   = (const float*)d_in[2];
    const float* bq   = (const float*)d_in[3];
    const float* Wk   = (const float*)d_in[4];
    const float* bk   = (const float*)d_in[5];
    const float* Wv   = (const float*)d_in[6];
    const float* bv   = (const float*)d_in[7];
    float* out = (float*)d_out;

    cudaFuncSetAttribute(qkv_kernel,    cudaFuncAttributeMaxDynamicSharedMemorySize, SMEM_TOTAL);
    cudaFuncSetAttribute(scores_kernel, cudaFuncAttributeMaxDynamicSharedMemorySize, SMEM_TOTAL);
    cudaFuncSetAttribute(pv_kernel,     cudaFuncAttributeMaxDynamicSharedMemorySize, SMEM_TOTAL);

    // 1) fp32 -> fp16 tiled-swizzled images
    convert_x_kernel<<<(unsigned)((size_t)Bsz * S * E / 8 / 256), 256>>>(x);
    convert_w_kernel<<<dim3(D / 32, E / 32, 3), 256>>>(Wq, Wk, Wv);

    // 2) Q, K, V projections in one launch
    qkv_kernel<<<dim3(512, 3), NTH, SMEM_TOTAL>>>(bq, bk, bv);

    // 3) scores + mask + exp + row partial sums
    scores_kernel<<<dim3(S / 128, S / 128, Bsz), NTH, SMEM_TOTAL>>>(mask);

    // 4) out = (P' @ V) / rowsum
    pv_kernel<<<dim3(D / 128, S / 128, Bsz), NTH, SMEM_TOTAL>>>(out);
}